// round 10
// baseline (speedup 1.0000x reference)
#include <cuda_runtime.h>

#define L 32768
#define E 1024
#define H 8
#define D 128
#define E4 256            // float4 per row
#define NB 256            // fused blocks (2 per SM, 1 wave)
#define RPB 128           // rows per fused block
#define TILE 8
#define NT (RPB/TILE)     // 16 tiles per block
#define RSQRT_D 0.08838834764831845f

typedef unsigned long long u64;

// ---------------- device scratch ----------------
__device__ float g_q[E];
__device__ float g_s[H][E];
__device__ float g_pm[NB * H];
__device__ float g_ps[NB * H];
__device__ float g_partial[NB][H][E];   // 8 MB (unnormalized, local max)
__device__ float g_w[H][E];
__device__ float g_attn[E];

#define FMA2(d, a, b, c) \
    asm("fma.rn.f32x2 %0, %1, %2, %3;" : "=l"(d) : "l"(a), "l"(b), "l"(c))

__device__ __forceinline__ u64 pack2(float a, float b) {
    u64 u; asm("mov.b64 %0, {%1, %2};" : "=l"(u) : "f"(a), "f"(b)); return u;
}
__device__ __forceinline__ float warp_sum(float v) {
    v += __shfl_xor_sync(0xffffffffu, v, 16);
    v += __shfl_xor_sync(0xffffffffu, v, 8);
    v += __shfl_xor_sync(0xffffffffu, v, 4);
    v += __shfl_xor_sync(0xffffffffu, v, 2);
    v += __shfl_xor_sync(0xffffffffu, v, 1);
    return v;
}

// ---------------- K1: q = Wq·x0 + bq ----------------
__global__ __launch_bounds__(256) void k_qproj(const float4* __restrict__ W4,
                                               const float4* __restrict__ X4,
                                               const float* __restrict__ bias) {
    int warp = threadIdx.x >> 5, lane = threadIdx.x & 31;
    int row = blockIdx.x * 8 + warp;
    const float4* wr = W4 + (size_t)row * E4;
    float4 a = make_float4(0.f, 0.f, 0.f, 0.f);
    #pragma unroll
    for (int i = 0; i < 8; i++) {
        float4 w = wr[lane + 32 * i];
        float4 x = X4[lane + 32 * i];
        a.x = fmaf(w.x, x.x, a.x); a.y = fmaf(w.y, x.y, a.y);
        a.z = fmaf(w.z, x.z, a.z); a.w = fmaf(w.w, x.w, a.w);
    }
    float acc = warp_sum((a.x + a.y) + (a.z + a.w));
    if (lane == 0) g_q[row] = acc + bias[row];
}

// ---------------- K2: s[h] = rsqrtD * Wk_h^T q_h ----------------
// grid 128 = (h, 16 segs of 16 float4); thread = (dgrp of 8 d, ec)
__global__ __launch_bounds__(256) void k_sproj(const float4* __restrict__ W4) {
    int h = blockIdx.x >> 4, seg = blockIdx.x & 15;
    int t = threadIdx.x;
    int dgrp = t >> 4, ec = t & 15;
    int e4 = seg * 16 + ec;
    __shared__ float qsh[D];
    __shared__ float4 pacc[16][16];
    if (t < D) qsh[t] = g_q[h * D + t];
    __syncthreads();
    const float4* Wk = W4 + (size_t)(E + h * D + dgrp * 8) * E4 + e4;
    float4 a = make_float4(0.f, 0.f, 0.f, 0.f);
    #pragma unroll
    for (int d = 0; d < 8; d++) {
        float4 w = Wk[(size_t)d * E4];
        float q = qsh[dgrp * 8 + d];
        a.x = fmaf(w.x, q, a.x); a.y = fmaf(w.y, q, a.y);
        a.z = fmaf(w.z, q, a.z); a.w = fmaf(w.w, q, a.w);
    }
    pacc[dgrp][ec] = a;
    __syncthreads();
    if (t < 16) {
        float4 r = pacc[0][t];
        #pragma unroll
        for (int k = 1; k < 16; k++) {
            float4 v = pacc[k][t];
            r.x += v.x; r.y += v.y; r.z += v.z; r.w += v.w;
        }
        r.x *= RSQRT_D; r.y *= RSQRT_D; r.z *= RSQRT_D; r.w *= RSQRT_D;
        ((float4*)g_s[h])[seg * 16 + t] = r;
    }
}

// ---------------- K3: fused logits + online softmax + weighted sum -------
// 256 threads, 8 warps = 4 head-pairs (hp) x 2 column-halves (ch).
// s lives in registers (8 LDG.128 in prologue); x staged via cp.async.
struct FSmem {
    float4 xbuf[2][TILE][E4];   // 64 KB double-buffered X tile
    float plg[2][TILE][H];      // ch-half partial logits
    u64   a2[TILE][H];          // packed exp weights
    float m_run[H], s_run[H], f_sh[H];
};

__device__ __forceinline__ void issue_loads(FSmem* s, int buf,
                                            const float4* __restrict__ X4,
                                            int row_base, int t) {
    #pragma unroll
    for (int i = 0; i < 8; i++) {
        int idx = t + 256 * i;                  // 0..2047
        int row = idx >> 8, col = idx & 255;
        unsigned sa = (unsigned)__cvta_generic_to_shared(&s->xbuf[buf][row][col]);
        const float4* g = X4 + (size_t)(row_base + row) * E4 + col;
        asm volatile("cp.async.cg.shared.global [%0], [%1], 16;"
                     :: "r"(sa), "l"(g) : "memory");
    }
    asm volatile("cp.async.commit_group;" ::: "memory");
}

__global__ __launch_bounds__(256, 2) void k_fused(const float4* __restrict__ X4) {
    extern __shared__ char smem_raw[];
    FSmem* s = reinterpret_cast<FSmem*>(smem_raw);
    int t = threadIdx.x, w = t >> 5, j = t & 31;
    int b = blockIdx.x;
    int row0 = b * RPB;
    int hp = w & 3, ch = w >> 2;

    // prologue: this warp's s slice into registers (2 heads x 128 cols)
    float4 sreg[4][2];
    #pragma unroll
    for (int fi = 0; fi < 4; fi++) {
        int f = ch * 128 + fi * 32 + j;
        sreg[fi][0] = ((const float4*)g_s[2 * hp])[f];
        sreg[fi][1] = ((const float4*)g_s[2 * hp + 1])[f];
    }
    if (t < H) { s->m_run[t] = -1e30f; s->s_run[t] = 0.f; }

    u64 accB[H][2];
    #pragma unroll
    for (int h = 0; h < H; h++) { accB[h][0] = 0ull; accB[h][1] = 0ull; }

    issue_loads(s, 0, X4, row0, t);

    for (int tile = 0; tile < NT; tile++) {
        int buf = tile & 1;
        asm volatile("cp.async.wait_group 0;" ::: "memory");
        __syncthreads();
        if (tile + 1 < NT) issue_loads(s, buf ^ 1, X4, row0 + (tile + 1) * TILE, t);

        // ---- phase A: scalar FFMA, s from registers ----
        float accA[TILE][2];
        #pragma unroll
        for (int r = 0; r < TILE; r++) { accA[r][0] = 0.f; accA[r][1] = 0.f; }

        #pragma unroll
        for (int fi = 0; fi < 4; fi++) {
            int f = ch * 128 + fi * 32 + j;
            float4 s0 = sreg[fi][0], s1 = sreg[fi][1];
            #pragma unroll
            for (int rc = 0; rc < 2; rc++) {
                float4 xv[4];
                #pragma unroll
                for (int rr = 0; rr < 4; rr++) xv[rr] = s->xbuf[buf][rc * 4 + rr][f];
                #pragma unroll
                for (int rr = 0; rr < 4; rr++) {
                    int r = rc * 4 + rr;
                    accA[r][0] = fmaf(xv[rr].x, s0.x, accA[r][0]);
                    accA[r][0] = fmaf(xv[rr].y, s0.y, accA[r][0]);
                    accA[r][0] = fmaf(xv[rr].z, s0.z, accA[r][0]);
                    accA[r][0] = fmaf(xv[rr].w, s0.w, accA[r][0]);
                    accA[r][1] = fmaf(xv[rr].x, s1.x, accA[r][1]);
                    accA[r][1] = fmaf(xv[rr].y, s1.y, accA[r][1]);
                    accA[r][1] = fmaf(xv[rr].z, s1.z, accA[r][1]);
                    accA[r][1] = fmaf(xv[rr].w, s1.w, accA[r][1]);
                }
            }
        }
        #pragma unroll
        for (int r = 0; r < TILE; r++)
            #pragma unroll
            for (int hh = 0; hh < 2; hh++) {
                float v = warp_sum(accA[r][hh]);
                if (j == 0) s->plg[ch][r][2 * hp + hh] = v;
            }
        __syncthreads();

        // ---- stats: 64-thread warp-parallel online softmax ----
        if (t < 64) {
            int h = t >> 3, r = t & 7;
            float z = s->plg[0][r][h] + s->plg[1][r][h];
            float mt = z;
            mt = fmaxf(mt, __shfl_xor_sync(0xffffffffu, mt, 4));
            mt = fmaxf(mt, __shfl_xor_sync(0xffffffffu, mt, 2));
            mt = fmaxf(mt, __shfl_xor_sync(0xffffffffu, mt, 1));
            float m_old = s->m_run[h];
            float m_new = fmaxf(m_old, mt);
            float e = __expf(z - m_new);
            s->a2[r][h] = pack2(e, e);
            float st = e;
            st += __shfl_xor_sync(0xffffffffu, st, 4);
            st += __shfl_xor_sync(0xffffffffu, st, 2);
            st += __shfl_xor_sync(0xffffffffu, st, 1);
            if (r == 0) {
                float fr = __expf(m_old - m_new);
                s->s_run[h] = s->s_run[h] * fr + st;
                s->m_run[h] = m_new;
                s->f_sh[h] = fr;
            }
        }
        __syncthreads();

        // ---- phase B: rescale + accumulate; thread t = column float4 t ----
        #pragma unroll
        for (int h = 0; h < H; h++) {
            float fh = s->f_sh[h];
            u64 f2 = pack2(fh, fh);
            FMA2(accB[h][0], accB[h][0], f2, 0ull);
            FMA2(accB[h][1], accB[h][1], f2, 0ull);
        }
        #pragma unroll
        for (int r = 0; r < TILE; r++) {
            ulonglong2 xv = *(const ulonglong2*)&s->xbuf[buf][r][t];
            const ulonglong2* ap = (const ulonglong2*)s->a2[r];
            #pragma unroll
            for (int hq = 0; hq < 4; hq++) {
                ulonglong2 aa = ap[hq];
                FMA2(accB[2 * hq][0],     aa.x, xv.x, accB[2 * hq][0]);
                FMA2(accB[2 * hq][1],     aa.x, xv.y, accB[2 * hq][1]);
                FMA2(accB[2 * hq + 1][0], aa.y, xv.x, accB[2 * hq + 1][0]);
                FMA2(accB[2 * hq + 1][1], aa.y, xv.y, accB[2 * hq + 1][1]);
            }
        }
    }

    #pragma unroll
    for (int h = 0; h < H; h++) {
        ulonglong2 v; v.x = accB[h][0]; v.y = accB[h][1];
        ((ulonglong2*)g_partial[b][h])[t] = v;
    }
    if (t < H) { g_pm[b * H + t] = s->m_run[t]; g_ps[b * H + t] = s->s_run[t]; }
}

// ---------------- K4: single-stage rescaled reduction + normalize --------
// grid 256 = (h, 32 col-groups of 8 float4); block 256 = 32 slotgrp x 8 col.
__global__ __launch_bounds__(256) void k_reduce() {
    int t = threadIdx.x;
    int h = blockIdx.x >> 5, cg = blockIdx.x & 31;
    int sg = t >> 3, c = t & 7;
    int out4 = h * 256 + cg * 8 + c;
    __shared__ float red[8];
    __shared__ float Msh, invSsh;
    __shared__ float4 wsum[8][8];

    // global per-head max + sum over 256 slots (redundant per block, L2-hot)
    float pmv = g_pm[t * H + h];
    float m = pmv;
    #pragma unroll
    for (int o = 16; o; o >>= 1) m = fmaxf(m, __shfl_xor_sync(0xffffffffu, m, o));
    if ((t & 31) == 0) red[t >> 5] = m;
    __syncthreads();
    if (t == 0) {
        float mm = red[0];
        #pragma unroll
        for (int k = 1; k < 8; k++) mm = fmaxf(mm, red[k]);
        Msh = mm;
    }
    __syncthreads();
    float M = Msh;
    float sp = g_ps[t * H + h] * __expf(pmv - M);
    sp = warp_sum(sp);
    if ((t & 31) == 0) red[t >> 5] = sp;
    __syncthreads();
    if (t == 0) {
        float ss = 0.f;
        #pragma unroll
        for (int k = 0; k < 8; k++) ss += red[k];
        invSsh = 1.0f / ss;
    }
    __syncthreads();

    // each thread: 8 slots (sg + 32k), rescale-accumulate
    const float4* P = (const float4*)g_partial;
    float4 acc = make_float4(0.f, 0.f, 0.f, 0.f);
    #pragma unroll
    for (int k = 0; k < 8; k++) {
        int sl = sg + 32 * k;
        float f = __expf(g_pm[sl * H + h] - M);
        float4 v = P[(size_t)sl * 2048 + out4];
        acc.x = fmaf(v.x, f, acc.x); acc.y = fmaf(v.y, f, acc.y);
        acc.z = fmaf(v.z, f, acc.z); acc.w = fmaf(v.w, f, acc.w);
    }
    // reduce over 4 slotgrps within warp (lane xor 8, 16)
    #pragma unroll
    for (int o = 8; o <= 16; o <<= 1) {
        acc.x += __shfl_xor_sync(0xffffffffu, acc.x, o);
        acc.y += __shfl_xor_sync(0xffffffffu, acc.y, o);
        acc.z += __shfl_xor_sync(0xffffffffu, acc.z, o);
        acc.w += __shfl_xor_sync(0xffffffffu, acc.w, o);
    }
    if ((t & 31) < 8) wsum[t >> 5][c] = acc;
    __syncthreads();
    if (t < 32) {
        int cc = t & 7, wp = t >> 3;            // wp 0..3
        float4 a = wsum[wp][cc], bv = wsum[wp + 4][cc];
        a.x += bv.x; a.y += bv.y; a.z += bv.z; a.w += bv.w;
        #pragma unroll
        for (int o = 8; o <= 16; o <<= 1) {
            a.x += __shfl_xor_sync(0xffffffffu, a.x, o);
            a.y += __shfl_xor_sync(0xffffffffu, a.y, o);
            a.z += __shfl_xor_sync(0xffffffffu, a.z, o);
            a.w += __shfl_xor_sync(0xffffffffu, a.w, o);
        }
        if (t < 8) {
            float invS = invSsh;
            a.x *= invS; a.y *= invS; a.z *= invS; a.w *= invS;
            ((float4*)g_w)[h * 256 + cg * 8 + t] = a;
        }
    }
}

// ---------------- K5: attn = Wv·w + bv ----------------
__global__ __launch_bounds__(256) void k_vproj(const float4* __restrict__ W4,
                                               const float* __restrict__ bias) {
    int warp = threadIdx.x >> 5, lane = threadIdx.x & 31;
    int row = blockIdx.x * 8 + warp;
    int h = row >> 7;
    const float4* wr = W4 + (size_t)(2 * E + row) * E4;
    const float4* v4 = (const float4*)g_w[h];
    float4 a = make_float4(0.f, 0.f, 0.f, 0.f);
    #pragma unroll
    for (int i = 0; i < 8; i++) {
        float4 w = wr[lane + 32 * i];
        float4 x = v4[lane + 32 * i];
        a.x = fmaf(w.x, x.x, a.x); a.y = fmaf(w.y, x.y, a.y);
        a.z = fmaf(w.z, x.z, a.z); a.w = fmaf(w.w, x.w, a.w);
    }
    float acc = warp_sum((a.x + a.y) + (a.z + a.w));
    if (lane == 0) g_attn[row] = acc + bias[2 * E + row];
}

// ---------------- K6: out = Wo·attn + bo ----------------
__global__ __launch_bounds__(256) void k_oproj(const float4* __restrict__ Wo4,
                                               const float* __restrict__ bo,
                                               float* __restrict__ out) {
    int warp = threadIdx.x >> 5, lane = threadIdx.x & 31;
    int row = blockIdx.x * 8 + warp;
    const float4* wr = Wo4 + (size_t)row * E4;
    const float4* v4 = (const float4*)g_attn;
    float4 a = make_float4(0.f, 0.f, 0.f, 0.f);
    #pragma unroll
    for (int i = 0; i < 8; i++) {
        float4 w = wr[lane + 32 * i];
        float4 x = v4[lane + 32 * i];
        a.x = fmaf(w.x, x.x, a.x); a.y = fmaf(w.y, x.y, a.y);
        a.z = fmaf(w.z, x.z, a.z); a.w = fmaf(w.w, x.w, a.w);
    }
    float acc = warp_sum((a.x + a.y) + (a.z + a.w));
    if (lane == 0) out[row] = acc + bo[row];
}

extern "C" void kernel_launch(void* const* d_in, const int* in_sizes, int n_in,
                              void* d_out, int out_size) {
    const float* x   = (const float*)d_in[0];   // [L, E]
    const float* Win = (const float*)d_in[1];   // [3E, E]
    const float* bin = (const float*)d_in[2];   // [3E]
    const float* Wo  = (const float*)d_in[3];   // [E, E]
    const float* bo  = (const float*)d_in[4];   // [E]
    float* out = (float*)d_out;

    const float4* X4   = (const float4*)x;
    const float4* Win4 = (const float4*)Win;
    const float4* Wo4  = (const float4*)Wo;

    cudaFuncSetAttribute(k_fused, cudaFuncAttributeMaxDynamicSharedMemorySize,
                         (int)sizeof(FSmem));

    k_qproj<<<128, 256>>>(Win4, X4, bin);
    k_sproj<<<128, 256>>>(Win4);
    k_fused<<<NB, 256, sizeof(FSmem)>>>(X4);
    k_reduce<<<256, 256>>>();
    k_vproj<<<128, 256>>>(Win4, bin);
    k_oproj<<<128, 256>>>(Wo4, bo, out);
}

// round 11
// speedup vs baseline: 1.2551x; 1.2551x over previous
#include <cuda_runtime.h>

#define L 32768
#define E 1024
#define H 8
#define D 128
#define E4 256            // float4 per row
#define NB 256            // fused blocks (2 per SM, 1 wave)
#define RPB 128           // rows per fused block
#define TILE 8
#define NT (RPB/TILE)     // 16 tiles per block
#define RSQRT_D 0.08838834764831845f

typedef unsigned long long u64;

// ---------------- device scratch ----------------
__device__ float g_q[E];
__device__ float g_s[H][E];
__device__ float g_pm[NB * H];
__device__ float g_ps[NB * H];
__device__ float g_fac[NB][H];          // exp(pm - M) per slot/head
__device__ float g_inv[H];              // 1/S per head
__device__ float g_partial[NB][H][E];   // 8 MB (unnormalized, local max)
__device__ float g_partial2[32][H][E];  // 1 MB group partials
__device__ float g_w[H][E];
__device__ float g_attn[E];

#define FMA2(d, a, b, c) \
    asm("fma.rn.f32x2 %0, %1, %2, %3;" : "=l"(d) : "l"(a), "l"(b), "l"(c))

__device__ __forceinline__ u64 pack2(float a, float b) {
    u64 u; asm("mov.b64 %0, {%1, %2};" : "=l"(u) : "f"(a), "f"(b)); return u;
}
__device__ __forceinline__ float unpack_add(u64 u) {
    float lo, hi; asm("mov.b64 {%0, %1}, %2;" : "=f"(lo), "=f"(hi) : "l"(u));
    return lo + hi;
}
__device__ __forceinline__ float warp_sum(float v) {
    v += __shfl_xor_sync(0xffffffffu, v, 16);
    v += __shfl_xor_sync(0xffffffffu, v, 8);
    v += __shfl_xor_sync(0xffffffffu, v, 4);
    v += __shfl_xor_sync(0xffffffffu, v, 2);
    v += __shfl_xor_sync(0xffffffffu, v, 1);
    return v;
}

// ---------------- K1: q = Wq·x0 + bq ----------------
__global__ __launch_bounds__(256) void k_qproj(const float4* __restrict__ W4,
                                               const float4* __restrict__ X4,
                                               const float* __restrict__ bias) {
    int warp = threadIdx.x >> 5, lane = threadIdx.x & 31;
    int row = blockIdx.x * 8 + warp;
    const float4* wr = W4 + (size_t)row * E4;
    float4 a = make_float4(0.f, 0.f, 0.f, 0.f);
    #pragma unroll
    for (int i = 0; i < 8; i++) {
        float4 w = wr[lane + 32 * i];
        float4 x = X4[lane + 32 * i];
        a.x = fmaf(w.x, x.x, a.x); a.y = fmaf(w.y, x.y, a.y);
        a.z = fmaf(w.z, x.z, a.z); a.w = fmaf(w.w, x.w, a.w);
    }
    float acc = warp_sum((a.x + a.y) + (a.z + a.w));
    if (lane == 0) g_q[row] = acc + bias[row];
}

// ---------------- K2: s[h] = rsqrtD * Wk_h^T q_h ----------------
__global__ __launch_bounds__(256) void k_sproj(const float4* __restrict__ W4) {
    int h = blockIdx.x >> 4, seg = blockIdx.x & 15;
    int t = threadIdx.x;
    int dgrp = t >> 4, ec = t & 15;
    int e4 = seg * 16 + ec;
    __shared__ float qsh[D];
    __shared__ float4 pacc[16][16];
    if (t < D) qsh[t] = g_q[h * D + t];
    __syncthreads();
    const float4* Wk = W4 + (size_t)(E + h * D + dgrp * 8) * E4 + e4;
    float4 a = make_float4(0.f, 0.f, 0.f, 0.f);
    #pragma unroll
    for (int d = 0; d < 8; d++) {
        float4 w = Wk[(size_t)d * E4];
        float q = qsh[dgrp * 8 + d];
        a.x = fmaf(w.x, q, a.x); a.y = fmaf(w.y, q, a.y);
        a.z = fmaf(w.z, q, a.z); a.w = fmaf(w.w, q, a.w);
    }
    pacc[dgrp][ec] = a;
    __syncthreads();
    if (t < 16) {
        float4 r = pacc[0][t];
        #pragma unroll
        for (int k = 1; k < 16; k++) {
            float4 v = pacc[k][t];
            r.x += v.x; r.y += v.y; r.z += v.z; r.w += v.w;
        }
        r.x *= RSQRT_D; r.y *= RSQRT_D; r.z *= RSQRT_D; r.w *= RSQRT_D;
        ((float4*)g_s[h])[seg * 16 + t] = r;
    }
}

// ---------------- K3: fused logits + online softmax + weighted sum -------
// 256 threads, 8 warps = 2 head-halves (hh) x 4 column-quarters (cq).
// s packed u64 in registers; all phase-A math is FMA2.
struct FSmem {
    float4 xbuf[2][TILE][E4];   // 64 KB double-buffered X tile
    float plg[4][TILE][H];      // per-column-quarter partial logits
    u64   a2[TILE][H];          // packed exp weights
    float m_run[H], s_run[H], f_sh[H];
};

__device__ __forceinline__ void issue_loads(FSmem* s, int buf,
                                            const float4* __restrict__ X4,
                                            int row_base, int t) {
    #pragma unroll
    for (int i = 0; i < 8; i++) {
        int idx = t + 256 * i;                  // 0..2047
        int row = idx >> 8, col = idx & 255;
        unsigned sa = (unsigned)__cvta_generic_to_shared(&s->xbuf[buf][row][col]);
        const float4* g = X4 + (size_t)(row_base + row) * E4 + col;
        asm volatile("cp.async.cg.shared.global [%0], [%1], 16;"
                     :: "r"(sa), "l"(g) : "memory");
    }
    asm volatile("cp.async.commit_group;" ::: "memory");
}

__global__ __launch_bounds__(256, 2) void k_fused(const float4* __restrict__ X4) {
    extern __shared__ char smem_raw[];
    FSmem* s = reinterpret_cast<FSmem*>(smem_raw);
    int t = threadIdx.x, w = t >> 5, j = t & 31;
    int b = blockIdx.x;
    int row0 = b * RPB;
    int hh = w >> 2, cq = w & 3;

    // prologue: this warp's packed s slice (4 heads x 2 float4-cols per lane)
    ulonglong2 sreg[2][4];                      // [fi][head k] each = 1 float4
    #pragma unroll
    for (int fi = 0; fi < 2; fi++) {
        int f = cq * 64 + fi * 32 + j;
        #pragma unroll
        for (int k = 0; k < 4; k++) {
            float4 sv = ((const float4*)g_s[hh * 4 + k])[f];
            sreg[fi][k] = *(ulonglong2*)&sv;
        }
    }
    if (t < H) { s->m_run[t] = -1e30f; s->s_run[t] = 0.f; }

    u64 accB[H][2];
    #pragma unroll
    for (int h = 0; h < H; h++) { accB[h][0] = 0ull; accB[h][1] = 0ull; }

    issue_loads(s, 0, X4, row0, t);

    for (int tile = 0; tile < NT; tile++) {
        int buf = tile & 1;
        asm volatile("cp.async.wait_group 0;" ::: "memory");
        __syncthreads();
        if (tile + 1 < NT) issue_loads(s, buf ^ 1, X4, row0 + (tile + 1) * TILE, t);

        // ---- phase A: packed FMA2, s from registers, x read once per warp --
        #pragma unroll
        for (int hr = 0; hr < 2; hr++) {        // 4-row halves (register cap)
            u64 acc[4][4];                      // [row rr][head k]
            #pragma unroll
            for (int rr = 0; rr < 4; rr++)
                #pragma unroll
                for (int k = 0; k < 4; k++) acc[rr][k] = 0ull;

            #pragma unroll
            for (int fi = 0; fi < 2; fi++) {
                int f = cq * 64 + fi * 32 + j;
                #pragma unroll
                for (int rr = 0; rr < 4; rr++) {
                    float4 xv = s->xbuf[buf][hr * 4 + rr][f];
                    ulonglong2 xp = *(ulonglong2*)&xv;
                    #pragma unroll
                    for (int k = 0; k < 4; k++) {
                        FMA2(acc[rr][k], xp.x, sreg[fi][k].x, acc[rr][k]);
                        FMA2(acc[rr][k], xp.y, sreg[fi][k].y, acc[rr][k]);
                    }
                }
            }
            #pragma unroll
            for (int rr = 0; rr < 4; rr++)
                #pragma unroll
                for (int k = 0; k < 4; k++) {
                    float v = warp_sum(unpack_add(acc[rr][k]));
                    if (j == 0) s->plg[cq][hr * 4 + rr][hh * 4 + k] = v;
                }
        }
        __syncthreads();

        // ---- stats: 64-thread warp-parallel online softmax ----
        if (t < 64) {
            int h = t >> 3, r = t & 7;
            float z = s->plg[0][r][h] + s->plg[1][r][h]
                    + s->plg[2][r][h] + s->plg[3][r][h];
            float mt = z;
            mt = fmaxf(mt, __shfl_xor_sync(0xffffffffu, mt, 4));
            mt = fmaxf(mt, __shfl_xor_sync(0xffffffffu, mt, 2));
            mt = fmaxf(mt, __shfl_xor_sync(0xffffffffu, mt, 1));
            float m_old = s->m_run[h];
            float m_new = fmaxf(m_old, mt);
            float e = __expf(z - m_new);
            s->a2[r][h] = pack2(e, e);
            float st = e;
            st += __shfl_xor_sync(0xffffffffu, st, 4);
            st += __shfl_xor_sync(0xffffffffu, st, 2);
            st += __shfl_xor_sync(0xffffffffu, st, 1);
            if (r == 0) {
                float fr = __expf(m_old - m_new);
                s->s_run[h] = s->s_run[h] * fr + st;
                s->m_run[h] = m_new;
                s->f_sh[h] = fr;
            }
        }
        __syncthreads();

        // ---- phase B: rescale + accumulate; thread t = column float4 t ----
        #pragma unroll
        for (int h = 0; h < H; h++) {
            float fh = s->f_sh[h];
            u64 f2 = pack2(fh, fh);
            FMA2(accB[h][0], accB[h][0], f2, 0ull);
            FMA2(accB[h][1], accB[h][1], f2, 0ull);
        }
        #pragma unroll
        for (int r = 0; r < TILE; r++) {
            ulonglong2 xv = *(const ulonglong2*)&s->xbuf[buf][r][t];
            const ulonglong2* ap = (const ulonglong2*)s->a2[r];
            #pragma unroll
            for (int hq = 0; hq < 4; hq++) {
                ulonglong2 aa = ap[hq];
                FMA2(accB[2 * hq][0],     aa.x, xv.x, accB[2 * hq][0]);
                FMA2(accB[2 * hq][1],     aa.x, xv.y, accB[2 * hq][1]);
                FMA2(accB[2 * hq + 1][0], aa.y, xv.x, accB[2 * hq + 1][0]);
                FMA2(accB[2 * hq + 1][1], aa.y, xv.y, accB[2 * hq + 1][1]);
            }
        }
    }

    #pragma unroll
    for (int h = 0; h < H; h++) {
        ulonglong2 v; v.x = accB[h][0]; v.y = accB[h][1];
        ((ulonglong2*)g_partial[b][h])[t] = v;
    }
    if (t < H) { g_pm[b * H + t] = s->m_run[t]; g_ps[b * H + t] = s->s_run[t]; }
}

// ---------------- K4a: global softmax stats + per-slot factors -----------
// 1 block, 256 threads; warp w owns head w.
__global__ __launch_bounds__(256) void k_gstats() {
    int t = threadIdx.x, w = t >> 5, j = t & 31;
    __shared__ float Msh[H], Ish[H];
    float pm[8];
    float m = -1e30f;
    #pragma unroll
    for (int k = 0; k < 8; k++) {
        pm[k] = g_pm[(j + 32 * k) * H + w];
        m = fmaxf(m, pm[k]);
    }
    #pragma unroll
    for (int o = 16; o; o >>= 1) m = fmaxf(m, __shfl_xor_sync(0xffffffffu, m, o));
    float ssum = 0.f;
    #pragma unroll
    for (int k = 0; k < 8; k++)
        ssum += g_ps[(j + 32 * k) * H + w] * __expf(pm[k] - m);
    ssum = warp_sum(ssum);
    if (j == 0) { Msh[w] = m; Ish[w] = 1.0f / ssum; }
    __syncthreads();
    #pragma unroll
    for (int h = 0; h < H; h++)
        g_fac[t][h] = __expf(g_pm[t * H + h] - Msh[h]);
    if (t < H) g_inv[t] = Ish[t];
}

// ---------------- K4b: rescaled 8-slot group reduce (512 blocks) ---------
__global__ __launch_bounds__(128) void k_reduce1() {
    int t = threadIdx.x;
    int out4 = blockIdx.x * 128 + t;            // 0..2047
    int h = out4 >> 8;
    int g = blockIdx.y;                         // 32 groups of 8 slots
    const float4* P = (const float4*)g_partial;
    float4 acc = make_float4(0.f, 0.f, 0.f, 0.f);
    #pragma unroll
    for (int k = 0; k < 8; k++) {
        int sl = g * 8 + k;
        float f = g_fac[sl][h];
        float4 v = P[(size_t)sl * 2048 + out4];
        acc.x = fmaf(v.x, f, acc.x); acc.y = fmaf(v.y, f, acc.y);
        acc.z = fmaf(v.z, f, acc.z); acc.w = fmaf(v.w, f, acc.w);
    }
    ((float4*)g_partial2)[(size_t)g * 2048 + out4] = acc;
}

// ---------------- K4c: final sum + normalize -----------------------------
__global__ __launch_bounds__(128) void k_reduce2() {
    int t = threadIdx.x;
    int out4 = blockIdx.x * 128 + t;
    int h = out4 >> 8;
    const float4* P = (const float4*)g_partial2;
    float4 acc = make_float4(0.f, 0.f, 0.f, 0.f);
    #pragma unroll
    for (int g = 0; g < 32; g++) {
        float4 v = P[(size_t)g * 2048 + out4];
        acc.x += v.x; acc.y += v.y; acc.z += v.z; acc.w += v.w;
    }
    float invS = g_inv[h];
    acc.x *= invS; acc.y *= invS; acc.z *= invS; acc.w *= invS;
    ((float4*)g_w)[out4] = acc;
}

// ---------------- K5: attn = Wv·w + bv ----------------
__global__ __launch_bounds__(256) void k_vproj(const float4* __restrict__ W4,
                                               const float* __restrict__ bias) {
    int warp = threadIdx.x >> 5, lane = threadIdx.x & 31;
    int row = blockIdx.x * 8 + warp;
    int h = row >> 7;
    const float4* wr = W4 + (size_t)(2 * E + row) * E4;
    const float4* v4 = (const float4*)g_w[h];
    float4 a = make_float4(0.f, 0.f, 0.f, 0.f);
    #pragma unroll
    for (int i = 0; i < 8; i++) {
        float4 w = wr[lane + 32 * i];
        float4 x = v4[lane + 32 * i];
        a.x = fmaf(w.x, x.x, a.x); a.y = fmaf(w.y, x.y, a.y);
        a.z = fmaf(w.z, x.z, a.z); a.w = fmaf(w.w, x.w, a.w);
    }
    float acc = warp_sum((a.x + a.y) + (a.z + a.w));
    if (lane == 0) g_attn[row] = acc + bias[2 * E + row];
}

// ---------------- K6: out = Wo·attn + bo ----------------
__global__ __launch_bounds__(256) void k_oproj(const float4* __restrict__ Wo4,
                                               const float* __restrict__ bo,
                                               float* __restrict__ out) {
    int warp = threadIdx.x >> 5, lane = threadIdx.x & 31;
    int row = blockIdx.x * 8 + warp;
    const float4* wr = Wo4 + (size_t)row * E4;
    const float4* v4 = (const float4*)g_attn;
    float4 a = make_float4(0.f, 0.f, 0.f, 0.f);
    #pragma unroll
    for (int i = 0; i < 8; i++) {
        float4 w = wr[lane + 32 * i];
        float4 x = v4[lane + 32 * i];
        a.x = fmaf(w.x, x.x, a.x); a.y = fmaf(w.y, x.y, a.y);
        a.z = fmaf(w.z, x.z, a.z); a.w = fmaf(w.w, x.w, a.w);
    }
    float acc = warp_sum((a.x + a.y) + (a.z + a.w));
    if (lane == 0) out[row] = acc + bo[row];
}

extern "C" void kernel_launch(void* const* d_in, const int* in_sizes, int n_in,
                              void* d_out, int out_size) {
    const float* x   = (const float*)d_in[0];   // [L, E]
    const float* Win = (const float*)d_in[1];   // [3E, E]
    const float* bin = (const float*)d_in[2];   // [3E]
    const float* Wo  = (const float*)d_in[3];   // [E, E]
    const float* bo  = (const float*)d_in[4];   // [E]
    float* out = (float*)d_out;

    const float4* X4   = (const float4*)x;
    const float4* Win4 = (const float4*)Win;
    const float4* Wo4  = (const float4*)Wo;

    cudaFuncSetAttribute(k_fused, cudaFuncAttributeMaxDynamicSharedMemorySize,
                         (int)sizeof(FSmem));

    k_qproj<<<128, 256>>>(Win4, X4, bin);
    k_sproj<<<128, 256>>>(Win4);
    k_fused<<<NB, 256, sizeof(FSmem)>>>(X4);
    k_gstats<<<1, 256>>>();
    k_reduce1<<<dim3(16, 32), 128>>>();
    k_reduce2<<<16, 128>>>();
    k_vproj<<<128, 256>>>(Win4, bin);
    k_oproj<<<128, 256>>>(Wo4, bo, out);
}

// round 12
// speedup vs baseline: 1.6629x; 1.3249x over previous
#include <cuda_runtime.h>

#define L 32768
#define E 1024
#define H 8
#define D 128
#define E4 256            // float4 per row
#define NB 256            // mega blocks (<=2/SM co-resident, 1 wave)
#define RPB 128           // rows per block in flash phase
#define TILE 8
#define NT (RPB/TILE)     // 16 tiles per block
#define RSQRT_D 0.08838834764831845f

typedef unsigned long long u64;

// ---------------- device scratch ----------------
__device__ float g_q[E];
__device__ float g_s[H][E];
__device__ float g_pm[NB * H];
__device__ float g_ps[NB * H];
__device__ float g_partial[NB][H][E];   // 8 MB (unnormalized, local max)
__device__ float g_partial2[32][H][E];  // 1 MB group partials
__device__ float g_w[H][E];
__device__ float g_attn[E];
__device__ unsigned g_ctr[8];           // grid-barrier counters (self-reset)

#define FMA2(d, a, b, c) \
    asm("fma.rn.f32x2 %0, %1, %2, %3;" : "=l"(d) : "l"(a), "l"(b), "l"(c))
#define ADD2(d, a, b) \
    asm("add.rn.f32x2 %0, %1, %2;" : "=l"(d) : "l"(a), "l"(b))

__device__ __forceinline__ u64 pack2(float a, float b) {
    u64 u; asm("mov.b64 %0, {%1, %2};" : "=l"(u) : "f"(a), "f"(b)); return u;
}
__device__ __forceinline__ float unpack_add(u64 u) {
    float lo, hi; asm("mov.b64 {%0, %1}, %2;" : "=f"(lo), "=f"(hi) : "l"(u));
    return lo + hi;
}
__device__ __forceinline__ float warp_sum(float v) {
    v += __shfl_xor_sync(0xffffffffu, v, 16);
    v += __shfl_xor_sync(0xffffffffu, v, 8);
    v += __shfl_xor_sync(0xffffffffu, v, 4);
    v += __shfl_xor_sync(0xffffffffu, v, 2);
    v += __shfl_xor_sync(0xffffffffu, v, 1);
    return v;
}
__device__ __forceinline__ float warp_max(float v) {
    v = fmaxf(v, __shfl_xor_sync(0xffffffffu, v, 16));
    v = fmaxf(v, __shfl_xor_sync(0xffffffffu, v, 8));
    v = fmaxf(v, __shfl_xor_sync(0xffffffffu, v, 4));
    v = fmaxf(v, __shfl_xor_sync(0xffffffffu, v, 2));
    v = fmaxf(v, __shfl_xor_sync(0xffffffffu, v, 1));
    return v;
}

// grid barrier: all NB blocks co-resident (verified occupancy), counter idx i.
__device__ __forceinline__ void gbar(int i, int tid) {
    __syncthreads();
    if (tid == 0) {
        __threadfence();
        atomicAdd(&g_ctr[i], 1u);
        while (((volatile unsigned*)g_ctr)[i] < NB) __nanosleep(128);
    }
    __syncthreads();
}

struct FSmem {
    float4 xbuf[2][TILE][E4];   // 64 KB double-buffered X tile
    float plg[4][TILE][H];      // per-column-quarter partial logits
    u64   a2[TILE][H];          // packed exp weights
    float m_run[H], s_run[H], f_sh[H];
};

__device__ __forceinline__ void issue_loads(FSmem* s, int buf,
                                            const float4* __restrict__ X4,
                                            int row_base, int t) {
    #pragma unroll
    for (int i = 0; i < 8; i++) {
        int idx = t + 256 * i;                  // 0..2047
        int row = idx >> 8, col = idx & 255;
        unsigned sa = (unsigned)__cvta_generic_to_shared(&s->xbuf[buf][row][col]);
        const float4* g = X4 + (size_t)(row_base + row) * E4 + col;
        asm volatile("cp.async.cg.shared.global [%0], [%1], 16;"
                     :: "r"(sa), "l"(g) : "memory");
    }
    asm volatile("cp.async.commit_group;" ::: "memory");
}

__global__ __launch_bounds__(256, 2) void k_mega(
        const float4* __restrict__ X4,
        const float4* __restrict__ Win4,
        const float*  __restrict__ bin,
        const float4* __restrict__ Wo4,
        const float*  __restrict__ bo,
        float* __restrict__ out) {
    extern __shared__ char smem_raw[];
    FSmem* s = reinterpret_cast<FSmem*>(smem_raw);
    float* red = (float*)smem_raw;              // scratch overlay (post-flash)
    int t = threadIdx.x, w = t >> 5, j = t & 31;
    int b = blockIdx.x;

    // ============ phase Q: q = Wq·x0 + bq (blocks 0..127) ============
    if (b < 128) {
        int row = b * 8 + w;
        const float4* wr = Win4 + (size_t)row * E4;
        float4 a = make_float4(0.f, 0.f, 0.f, 0.f);
        #pragma unroll
        for (int i = 0; i < 8; i++) {
            float4 ww = wr[j + 32 * i];
            float4 x = X4[j + 32 * i];
            a.x = fmaf(ww.x, x.x, a.x); a.y = fmaf(ww.y, x.y, a.y);
            a.z = fmaf(ww.z, x.z, a.z); a.w = fmaf(ww.w, x.w, a.w);
        }
        float acc = warp_sum((a.x + a.y) + (a.z + a.w));
        if (j == 0) g_q[row] = acc + bin[row];
    }
    gbar(0, t);

    // ============ phase S: s[h] = rsqrtD * Wk_h^T q_h (blocks 0..127) ====
    if (b < 128) {
        int h = b >> 4, seg = b & 15;
        int dgrp = t >> 4, ec = t & 15;
        int e4 = seg * 16 + ec;
        float* qsh = red;                       // [128]
        float4* pacc = (float4*)(red + 128);    // [16][16]
        if (t < D) qsh[t] = __ldcg(&g_q[h * D + t]);
        __syncthreads();
        const float4* Wk = Win4 + (size_t)(E + h * D + dgrp * 8) * E4 + e4;
        float4 a = make_float4(0.f, 0.f, 0.f, 0.f);
        #pragma unroll
        for (int d = 0; d < 8; d++) {
            float4 ww = Wk[(size_t)d * E4];
            float q = qsh[dgrp * 8 + d];
            a.x = fmaf(ww.x, q, a.x); a.y = fmaf(ww.y, q, a.y);
            a.z = fmaf(ww.z, q, a.z); a.w = fmaf(ww.w, q, a.w);
        }
        pacc[dgrp * 16 + ec] = a;
        __syncthreads();
        if (t < 16) {
            float4 r = pacc[t];
            #pragma unroll
            for (int k = 1; k < 16; k++) {
                float4 v = pacc[k * 16 + t];
                r.x += v.x; r.y += v.y; r.z += v.z; r.w += v.w;
            }
            r.x *= RSQRT_D; r.y *= RSQRT_D; r.z *= RSQRT_D; r.w *= RSQRT_D;
            ((float4*)g_s[h])[seg * 16 + t] = r;
        }
    }
    gbar(1, t);

    // ============ phase F: fused logits + online softmax + weighted sum ==
    {
        int row0 = b * RPB;
        int hh = w >> 2, cq = w & 3;

        ulonglong2 sreg[2][4];                  // [fi][head k]
        #pragma unroll
        for (int fi = 0; fi < 2; fi++) {
            int f = cq * 64 + fi * 32 + j;
            #pragma unroll
            for (int k = 0; k < 4; k++) {
                float4 sv = __ldcg(((const float4*)g_s[hh * 4 + k]) + f);
                sreg[fi][k] = *(ulonglong2*)&sv;
            }
        }
        __syncthreads();                        // red overlay dead before FSmem use
        if (t < H) { s->m_run[t] = -1e30f; s->s_run[t] = 0.f; }

        u64 accB[H][2];
        #pragma unroll
        for (int h = 0; h < H; h++) { accB[h][0] = 0ull; accB[h][1] = 0ull; }

        issue_loads(s, 0, X4, row0, t);

        for (int tile = 0; tile < NT; tile++) {
            int buf = tile & 1;
            asm volatile("cp.async.wait_group 0;" ::: "memory");
            __syncthreads();
            if (tile + 1 < NT) issue_loads(s, buf ^ 1, X4, row0 + (tile + 1) * TILE, t);

            // ---- phase A: packed FMA2 + butterfly reduce-scatter ----
            #pragma unroll
            for (int hr = 0; hr < 2; hr++) {
                u64 cur[16];                    // i = rr*4 + k
                #pragma unroll
                for (int i = 0; i < 16; i++) cur[i] = 0ull;
                #pragma unroll
                for (int fi = 0; fi < 2; fi++) {
                    int f = cq * 64 + fi * 32 + j;
                    #pragma unroll
                    for (int rr = 0; rr < 4; rr++) {
                        float4 xv = s->xbuf[buf][hr * 4 + rr][f];
                        ulonglong2 xp = *(ulonglong2*)&xv;
                        #pragma unroll
                        for (int k = 0; k < 4; k++) {
                            FMA2(cur[rr * 4 + k], xp.x, sreg[fi][k].x, cur[rr * 4 + k]);
                            FMA2(cur[rr * 4 + k], xp.y, sreg[fi][k].y, cur[rr * 4 + k]);
                        }
                    }
                }
                // butterfly: 16 u64 sums -> 1 complete sum per lane-pair
                bool b16 = (j & 16);
                u64 n8[8];
                #pragma unroll
                for (int m = 0; m < 8; m++) {
                    u64 snd = b16 ? cur[m] : cur[m + 8];
                    u64 kp  = b16 ? cur[m + 8] : cur[m];
                    u64 rc = __shfl_xor_sync(0xffffffffu, snd, 16);
                    ADD2(n8[m], kp, rc);
                }
                bool b8 = (j & 8);
                u64 n4[4];
                #pragma unroll
                for (int m = 0; m < 4; m++) {
                    u64 snd = b8 ? n8[m] : n8[m + 4];
                    u64 kp  = b8 ? n8[m + 4] : n8[m];
                    u64 rc = __shfl_xor_sync(0xffffffffu, snd, 8);
                    ADD2(n4[m], kp, rc);
                }
                bool b4 = (j & 4);
                u64 n2[2];
                #pragma unroll
                for (int m = 0; m < 2; m++) {
                    u64 snd = b4 ? n4[m] : n4[m + 2];
                    u64 kp  = b4 ? n4[m + 2] : n4[m];
                    u64 rc = __shfl_xor_sync(0xffffffffu, snd, 4);
                    ADD2(n2[m], kp, rc);
                }
                bool b2 = (j & 2);
                u64 snd = b2 ? n2[0] : n2[1];
                u64 kp  = b2 ? n2[1] : n2[0];
                u64 rc = __shfl_xor_sync(0xffffffffu, snd, 2);
                u64 n1; ADD2(n1, kp, rc);
                rc = __shfl_xor_sync(0xffffffffu, n1, 1);
                ADD2(n1, n1, rc);
                float z = unpack_add(n1);
                int idx = ((j >> 4) & 1) * 8 + ((j >> 3) & 1) * 4
                        + ((j >> 2) & 1) * 2 + ((j >> 1) & 1);
                if (!(j & 1))
                    s->plg[cq][hr * 4 + (idx >> 2)][hh * 4 + (idx & 3)] = z;
            }
            __syncthreads();

            // ---- stats: 64-thread warp-parallel online softmax ----
            if (t < 64) {
                int h = t >> 3, r = t & 7;
                float z = s->plg[0][r][h] + s->plg[1][r][h]
                        + s->plg[2][r][h] + s->plg[3][r][h];
                float mt = z;
                mt = fmaxf(mt, __shfl_xor_sync(0xffffffffu, mt, 4));
                mt = fmaxf(mt, __shfl_xor_sync(0xffffffffu, mt, 2));
                mt = fmaxf(mt, __shfl_xor_sync(0xffffffffu, mt, 1));
                float m_old = s->m_run[h];
                float m_new = fmaxf(m_old, mt);
                float e = __expf(z - m_new);
                s->a2[r][h] = pack2(e, e);
                float st = e;
                st += __shfl_xor_sync(0xffffffffu, st, 4);
                st += __shfl_xor_sync(0xffffffffu, st, 2);
                st += __shfl_xor_sync(0xffffffffu, st, 1);
                if (r == 0) {
                    float fr = __expf(m_old - m_new);
                    s->s_run[h] = s->s_run[h] * fr + st;
                    s->m_run[h] = m_new;
                    s->f_sh[h] = fr;
                }
            }
            __syncthreads();

            // ---- phase B: rescale + accumulate; thread t = column f4 t ----
            #pragma unroll
            for (int h = 0; h < H; h++) {
                float fh = s->f_sh[h];
                u64 f2 = pack2(fh, fh);
                FMA2(accB[h][0], accB[h][0], f2, 0ull);
                FMA2(accB[h][1], accB[h][1], f2, 0ull);
            }
            #pragma unroll
            for (int r = 0; r < TILE; r++) {
                ulonglong2 xv = *(const ulonglong2*)&s->xbuf[buf][r][t];
                const ulonglong2* ap = (const ulonglong2*)s->a2[r];
                #pragma unroll
                for (int hq = 0; hq < 4; hq++) {
                    ulonglong2 aa = ap[hq];
                    FMA2(accB[2 * hq][0],     aa.x, xv.x, accB[2 * hq][0]);
                    FMA2(accB[2 * hq][1],     aa.x, xv.y, accB[2 * hq][1]);
                    FMA2(accB[2 * hq + 1][0], aa.y, xv.x, accB[2 * hq + 1][0]);
                    FMA2(accB[2 * hq + 1][1], aa.y, xv.y, accB[2 * hq + 1][1]);
                }
            }
        }

        #pragma unroll
        for (int h = 0; h < H; h++) {
            ulonglong2 v; v.x = accB[h][0]; v.y = accB[h][1];
            ((ulonglong2*)g_partial[b][h])[t] = v;
        }
        if (t < H) { g_pm[b * H + t] = s->m_run[t]; g_ps[b * H + t] = s->s_run[t]; }
    }
    gbar(2, t);

    // ============ phase R1: rescaled 8-slot group reduce =================
    {
        int g = b >> 3, h = b & 7;
        int out4 = h * 256 + t;
        float pmv = __ldcg(&g_pm[t * H + h]);   // t covers all 256 slots
        float m = warp_max(pmv);
        if (j == 0) red[w] = m;
        __syncthreads();
        if (t == 0) {
            float mm = red[0];
            #pragma unroll
            for (int k = 1; k < 8; k++) mm = fmaxf(mm, red[k]);
            red[8] = mm;
        }
        __syncthreads();
        float M = red[8];
        const float4* P = (const float4*)g_partial;
        float4 acc = make_float4(0.f, 0.f, 0.f, 0.f);
        #pragma unroll
        for (int k = 0; k < 8; k++) {
            int sl = g * 8 + k;
            float f = __expf(__ldcg(&g_pm[sl * H + h]) - M);
            float4 v = __ldcg(P + (size_t)sl * 2048 + out4);
            acc.x = fmaf(v.x, f, acc.x); acc.y = fmaf(v.y, f, acc.y);
            acc.z = fmaf(v.z, f, acc.z); acc.w = fmaf(v.w, f, acc.w);
        }
        ((float4*)g_partial2)[(size_t)g * 2048 + out4] = acc;
    }
    gbar(3, t);

    // ============ phase R2: final sum + normalize (blocks 0..7) ==========
    if (b < 8) {
        int h = b;
        int out4 = h * 256 + t;
        float pmv = __ldcg(&g_pm[t * H + h]);
        float m = warp_max(pmv);
        if (j == 0) red[w] = m;
        __syncthreads();
        if (t == 0) {
            float mm = red[0];
            #pragma unroll
            for (int k = 1; k < 8; k++) mm = fmaxf(mm, red[k]);
            red[8] = mm;
        }
        __syncthreads();
        float M = red[8];
        float sp = __ldcg(&g_ps[t * H + h]) * __expf(pmv - M);
        sp = warp_sum(sp);
        if (j == 0) red[16 + w] = sp;
        __syncthreads();
        if (t == 0) {
            float ss = 0.f;
            #pragma unroll
            for (int k = 0; k < 8; k++) ss += red[16 + k];
            red[9] = 1.0f / ss;
        }
        __syncthreads();
        float invS = red[9];
        const float4* P2 = (const float4*)g_partial2;
        float4 acc = make_float4(0.f, 0.f, 0.f, 0.f);
        #pragma unroll
        for (int g = 0; g < 32; g++) {
            float4 v = __ldcg(P2 + (size_t)g * 2048 + out4);
            acc.x += v.x; acc.y += v.y; acc.z += v.z; acc.w += v.w;
        }
        acc.x *= invS; acc.y *= invS; acc.z *= invS; acc.w *= invS;
        ((float4*)g_w)[out4] = acc;
    }
    gbar(4, t);

    // ============ phase V: attn = Wv·w + bv (blocks 0..127) ==============
    if (b < 128) {
        int row = b * 8 + w;
        int h = row >> 7;
        const float4* wr = Win4 + (size_t)(2 * E + row) * E4;
        const float4* v4 = (const float4*)g_w[h];
        float4 a = make_float4(0.f, 0.f, 0.f, 0.f);
        #pragma unroll
        for (int i = 0; i < 8; i++) {
            float4 ww = wr[j + 32 * i];
            float4 x = __ldcg(v4 + j + 32 * i);
            a.x = fmaf(ww.x, x.x, a.x); a.y = fmaf(ww.y, x.y, a.y);
            a.z = fmaf(ww.z, x.z, a.z); a.w = fmaf(ww.w, x.w, a.w);
        }
        float acc = warp_sum((a.x + a.y) + (a.z + a.w));
        if (j == 0) g_attn[row] = acc + bin[2 * E + row];
    }
    gbar(5, t);

    // ============ phase O: out = Wo·attn + bo (blocks 0..127) ============
    if (b < 128) {
        int row = b * 8 + w;
        const float4* wr = Wo4 + (size_t)row * E4;
        const float4* v4 = (const float4*)g_attn;
        float4 a = make_float4(0.f, 0.f, 0.f, 0.f);
        #pragma unroll
        for (int i = 0; i < 8; i++) {
            float4 ww = wr[j + 32 * i];
            float4 x = __ldcg(v4 + j + 32 * i);
            a.x = fmaf(ww.x, x.x, a.x); a.y = fmaf(ww.y, x.y, a.y);
            a.z = fmaf(ww.z, x.z, a.z); a.w = fmaf(ww.w, x.w, a.w);
        }
        float acc = warp_sum((a.x + a.y) + (a.z + a.w));
        if (j == 0) out[row] = acc + bo[row];
    }

    // ============ counter self-reset (last finisher) =====================
    __syncthreads();
    if (t == 0) {
        __threadfence();
        if (atomicAdd(&g_ctr[6], 1u) == NB - 1) {
            #pragma unroll
            for (int i = 0; i < 7; i++) g_ctr[i] = 0;
            __threadfence();
        }
    }
}

extern "C" void kernel_launch(void* const* d_in, const int* in_sizes, int n_in,
                              void* d_out, int out_size) {
    const float* x   = (const float*)d_in[0];   // [L, E]
    const float* Win = (const float*)d_in[1];   // [3E, E]
    const float* bin = (const float*)d_in[2];   // [3E]
    const float* Wo  = (const float*)d_in[3];   // [E, E]
    const float* bo  = (const float*)d_in[4];   // [E]
    float* out = (float*)d_out;

    cudaFuncSetAttribute(k_mega, cudaFuncAttributeMaxDynamicSharedMemorySize,
                         (int)sizeof(FSmem));

    k_mega<<<NB, 256, sizeof(FSmem)>>>((const float4*)x, (const float4*)Win,
                                       bin, (const float4*)Wo, bo, out);
}